// round 16
// baseline (speedup 1.0000x reference)
#include <cuda_runtime.h>
#include <cuda_bf16.h>
#include <cuda_fp16.h>
#include <mma.h>
#include <math.h>
#include <stdint.h>

using namespace nvcuda;

#define S_   1024
#define DM_  1024
#define B_   8
#define H_   16
#define D_   64

// ---------------- scratch (__device__ globals; no allocation) ----------------
__device__ __half g_Qh[B_*H_*S_*D_];   // projected Q (pre-scaled by 1/32) fp16
__device__ __half g_Kh[B_*H_*S_*D_];   // projected K
__device__ __half g_Vh[B_*H_*S_*D_];   // projected V
__device__ __half g_Ac0[B_*S_*DM_];    // converted Q input; then X fp16
__device__ __half g_Ac1[B_*S_*DM_];    // converted K input
__device__ __half g_Ac2[B_*S_*DM_];    // converted V input
__device__ __half g_W4[4*DM_*DM_];     // transposed fp16 weights [n][k]: Wq,Wk,Wv,Wo

// ---------------- helpers ----------------
__device__ __forceinline__ uint32_t smem_u32(const void* p) {
    uint32_t a;
    asm("{ .reg .u64 t; cvta.to.shared.u64 t, %1; cvt.u32.u64 %0, t; }"
        : "=r"(a) : "l"(p));
    return a;
}
__device__ __forceinline__ void cp16(uint32_t dst, const void* src) {
    asm volatile("cp.async.cg.shared.global [%0], [%1], 16;" :: "r"(dst), "l"(src));
}
__device__ __forceinline__ uint32_t pack2h(float a, float b) {
    __half ha = __float2half_rn(a), hb = __float2half_rn(b);
    return (uint32_t)__half_as_ushort(ha) |
           ((uint32_t)__half_as_ushort(hb) << 16);
}
__device__ __forceinline__ void ldsm4(uint32_t* r, uint32_t addr) {
    asm volatile("ldmatrix.sync.aligned.m8n8.x4.shared.b16 {%0,%1,%2,%3}, [%4];"
        : "=r"(r[0]), "=r"(r[1]), "=r"(r[2]), "=r"(r[3]) : "r"(addr));
}
__device__ __forceinline__ void ldsm4t(uint32_t* r, uint32_t addr) {
    asm volatile("ldmatrix.sync.aligned.m8n8.x4.trans.shared.b16 {%0,%1,%2,%3}, [%4];"
        : "=r"(r[0]), "=r"(r[1]), "=r"(r[2]), "=r"(r[3]) : "r"(addr));
}
__device__ __forceinline__ void mma16816(float* c,
    uint32_t a0, uint32_t a1, uint32_t a2, uint32_t a3, uint32_t b0, uint32_t b1) {
    asm volatile(
        "mma.sync.aligned.m16n8k16.row.col.f32.f16.f16.f32 "
        "{%0,%1,%2,%3}, {%4,%5,%6,%7}, {%8,%9}, {%0,%1,%2,%3};"
        : "+f"(c[0]), "+f"(c[1]), "+f"(c[2]), "+f"(c[3])
        : "r"(a0), "r"(a1), "r"(a2), "r"(a3), "r"(b0), "r"(b1));
}

// ---------------- conversion kernels (batched over z) ----------------
__global__ __launch_bounds__(256) void cvt_act_h3(
    const float4* __restrict__ Q, const float4* __restrict__ K,
    const float4* __restrict__ V, int n4)
{
    int i = blockIdx.x * 256 + threadIdx.x;
    if (i >= n4) return;
    int z = blockIdx.y;
    const float4* src = (z == 0) ? Q : (z == 1) ? K : V;
    uint2* dst = (uint2*)((z == 0) ? g_Ac0 : (z == 1) ? g_Ac1 : g_Ac2);
    float4 v = src[i];
    uint2 h;
    h.x = pack2h(v.x, v.y);
    h.y = pack2h(v.z, v.w);
    dst[i] = h;
}

// weight transpose fp16, 4-way batch: z<3 src=W[h][k][d] (n=h*64+d); z=3 src=Wo[k][n]
__global__ __launch_bounds__(256) void split_wT_h4(
    const float* __restrict__ Wq, const float* __restrict__ Wk,
    const float* __restrict__ Wv, const float* __restrict__ Wo)
{
    __shared__ float t[32][33];
    int k0 = blockIdx.x * 32, n0 = blockIdx.y * 32;
    int z = blockIdx.z;
    const float* W = (z == 0) ? Wq : (z == 1) ? Wk : (z == 2) ? Wv : Wo;
    __half* out = g_W4 + (size_t)z * DM_ * DM_;
    int tx = threadIdx.x, ty = threadIdx.y;
    #pragma unroll
    for (int i = 0; i < 4; i++) {
        int k = k0 + ty + 8*i, n = n0 + tx;
        float v = (z < 3) ? W[(((size_t)(n >> 6)) * 1024 + k) * 64 + (n & 63)]
                          : W[(size_t)k * 1024 + n];
        t[ty + 8*i][tx] = v;
    }
    __syncthreads();
    #pragma unroll
    for (int i = 0; i < 4; i++) {
        int n = n0 + ty + 8*i, k = k0 + tx;
        out[(size_t)n * 1024 + k] = __float2half_rn(t[tx][ty + 8*i]);
    }
}

// ---------------- fragment typedefs / sizes ----------------
#define LDSM   40
#define MATB   (128 * LDSM * 2)
#define STAGEB1 (2 * MATB)                 // 20480 per stage (A + B)
#define EPLD   132
#define GSMEM1 (3 * STAGEB1 + 16 * 128 * 4)   // 69632; epilogue 67584 fits
#define GSMEMO (3 * STAGEB1 + 16 * 128 * 4)

typedef wmma::fragment<wmma::matrix_a, 16,16,16, __half, wmma::row_major> HFragA;
typedef wmma::fragment<wmma::matrix_b, 16,16,16, __half, wmma::col_major> HFragB;
typedef wmma::fragment<wmma::accumulator, 16,16,16, float> FragC;

// ---------------- fp16 single-pass GEMM stage loader ------------------------
__device__ __forceinline__ void issue_stage_h1(
    const __half* __restrict__ Ah, const __half* __restrict__ Bh,
    uint32_t sbase, int stage, int m0, int n0, int k0, int tid)
{
    #pragma unroll
    for (int u = 0; u < 8; u++) {
        int chunk = u * 128 + tid;
        int mat = chunk >> 9;
        int r   = (chunk >> 2) & 127;
        int c   = chunk & 3;
        const __half* g = (mat == 0)
            ? Ah + (size_t)(m0 + r) * 1024 + k0 + c * 8
            : Bh + (size_t)(n0 + r) * 1024 + k0 + c * 8;
        uint32_t dst = sbase + (uint32_t)(stage * STAGEB1 + mat * MATB + r * (LDSM*2) + c * 16);
        cp16(dst, g);
    }
    asm volatile("cp.async.commit_group;" ::: "memory");
}

// ---------------- fp16 GEMM mainloop (3-stage, 1 sync/iter) -----------------
#define GEMM_MAINLOOP(Ah, Bh)                                                  \
    issue_stage_h1(Ah, Bh, sbase, 0, m0, n0, 0, tid);                          \
    issue_stage_h1(Ah, Bh, sbase, 1, m0, n0, 32, tid);                         \
    __syncthreads();                                                           \
    FragC acc[4][4];                                                           \
    _Pragma("unroll")                                                          \
    for (int i = 0; i < 4; i++)                                                \
        _Pragma("unroll")                                                      \
        for (int j = 0; j < 4; j++)                                            \
            wmma::load_matrix_sync(acc[i][j], sBias + wn*64 + j*16, 128,       \
                                   wmma::mem_row_major);                       \
    for (int kc = 0; kc < 32; kc++) {                                          \
        if (kc < 31) { asm volatile("cp.async.wait_group 1;" ::: "memory"); }  \
        else         { asm volatile("cp.async.wait_group 0;" ::: "memory"); }  \
        __syncthreads();                                                       \
        if (kc + 2 < 32)                                                       \
            issue_stage_h1(Ah, Bh, sbase, (kc + 2) % 3, m0, n0,                \
                           (kc + 2) * 32, tid);                                \
        const __half* stg = (const __half*)(sm + (kc % 3) * STAGEB1);          \
        const __half* sAh = stg;                                               \
        const __half* sBh = stg + 128 * LDSM;                                  \
        _Pragma("unroll")                                                      \
        for (int ks = 0; ks < 2; ks++) {                                       \
            HFragA ah[4];                                                      \
            HFragB bh[4];                                                      \
            _Pragma("unroll")                                                  \
            for (int i = 0; i < 4; i++)                                        \
                wmma::load_matrix_sync(ah[i], sAh + (wm*64 + i*16) * LDSM      \
                                       + ks*16, LDSM);                         \
            _Pragma("unroll")                                                  \
            for (int j = 0; j < 4; j++)                                        \
                wmma::load_matrix_sync(bh[j], sBh + (wn*64 + j*16) * LDSM      \
                                       + ks*16, LDSM);                         \
            _Pragma("unroll")                                                  \
            for (int i = 0; i < 4; i++)                                        \
                _Pragma("unroll")                                              \
                for (int j = 0; j < 4; j++)                                    \
                    wmma::mma_sync(acc[i][j], ah[i], bh[j], acc[i][j]);        \
        }                                                                      \
    }

// ---------------- batched QKV projections ------------------------------------
__global__ __launch_bounds__(128, 2) void mma_gemm_h1b(
    const float* __restrict__ bq, const float* __restrict__ bk,
    const float* __restrict__ bv)
{
    extern __shared__ char sm[];
    float* sBias = (float*)(sm + 3 * STAGEB1);
    const uint32_t sbase = smem_u32(sm);
    const int tid = threadIdx.x;
    const int wid = tid >> 5;
    const int m0 = blockIdx.y * 128;
    const int n0 = blockIdx.x * 128;
    const int z  = blockIdx.z;
    const int wm = wid >> 1;
    const int wn = wid & 1;

    const __half* Ah = (z == 0) ? g_Ac0 : (z == 1) ? g_Ac1 : g_Ac2;
    const __half* Bh = g_W4 + (size_t)z * DM_ * DM_;
    const float* bias = (z == 0) ? bq : (z == 1) ? bk : bv;
    __half* outH = (z == 0) ? g_Qh : (z == 1) ? g_Kh : g_Vh;
    const float osc = (z == 0) ? 0.03125f : 1.0f;   // fold 1/32 into Q (exact)

    for (int idx = tid; idx < 16 * 128; idx += 128)
        sBias[idx] = bias[n0 + (idx & 127)];

    GEMM_MAINLOOP(Ah, Bh)

    __syncthreads();
    float* sEpi = (float*)sm;
    #pragma unroll
    for (int i = 0; i < 4; i++)
        #pragma unroll
        for (int j = 0; j < 4; j++)
            wmma::store_matrix_sync(sEpi + (wm*64 + i*16) * EPLD + wn*64 + j*16,
                                    acc[i][j], EPLD, wmma::mem_row_major);
    __syncthreads();

    #pragma unroll
    for (int u = 0; u < 64; u++) {
        int e2 = u * 128 + tid;
        int r = e2 >> 6;
        int c = (e2 & 63) * 2;
        float v0 = sEpi[r * EPLD + c]     * osc;
        float v1 = sEpi[r * EPLD + c + 1] * osc;
        uint32_t hv = pack2h(v0, v1);
        const int m = m0 + r, n = n0 + c;
        const int b = m >> 10, srow = m & 1023;
        const int h = n >> 6,  d = n & 63;
        size_t addr = ((((size_t)(b*16 + h)) * 1024 + srow) * 64 + d);
        *(uint32_t*)(outH + addr) = hv;
    }
}

// ---------------- output projection (fp32 out) -------------------------------
__global__ __launch_bounds__(128, 2) void mma_gemm_h1f(
    const float* __restrict__ bias, float* __restrict__ outF)
{
    extern __shared__ char sm[];
    float* sBias = (float*)(sm + 3 * STAGEB1);
    const uint32_t sbase = smem_u32(sm);
    const int tid = threadIdx.x;
    const int wid = tid >> 5;
    const int m0 = blockIdx.y * 128;
    const int n0 = blockIdx.x * 128;
    const int wm = wid >> 1;
    const int wn = wid & 1;

    const __half* Ah = g_Ac0;                         // X fp16
    const __half* Bh = g_W4 + (size_t)3 * DM_ * DM_;  // Wo fp16 [n][k]

    for (int idx = tid; idx < 16 * 128; idx += 128)
        sBias[idx] = bias[n0 + (idx & 127)];

    GEMM_MAINLOOP(Ah, Bh)

    #pragma unroll
    for (int i = 0; i < 4; i++) {
        const int m = m0 + wm*64 + i*16;
        #pragma unroll
        for (int j = 0; j < 4; j++) {
            const int n = n0 + wn*64 + j*16;
            wmma::store_matrix_sync(outF + (size_t)m * 1024 + n, acc[i][j],
                                    1024, wmma::mem_row_major);
        }
    }
}

// ---------------- flash attention v7: 3-stage KV, 1 sync/tile ----------------
#define ALD 72
#define SLD 68
#define TQB 9216
#define oQ   0                          // 2 groups x 1 fp16 tile  18432
#define oKV  18432                      // 3 stages x 2 tiles      55296
#define ATTN_SMEM 73728
#define KVSTG (2 * TQB)

__global__ __launch_bounds__(256, 2) void attn_mma(const int* __restrict__ pad)
{
    extern __shared__ char sm[];
    const uint32_t sbase = smem_u32(sm);
    const int tid  = threadIdx.x;
    const int w    = tid >> 5, lane = tid & 31;
    const int g    = w >> 2,   wr   = w & 3;
    const int bx   = blockIdx.x;
    const int bh   = blockIdx.y;
    const int b    = bh >> 4, h = bh & 15;
    const int padb = pad[b];
    const int tlim = S_ - padb;
    const int qt   = bx * 2 + g;
    const int q0   = qt * 64;
    const size_t hoff = (size_t)bh * S_ * D_;

    const uint32_t sQbase = sbase + oQ + (uint32_t)g * TQB;
    const int jtLast = (padb == 0) ? 15 : min(bx * 2 + 1, (tlim - 1) >> 6);

    // preload group A: Q tiles (both groups) + KV stage 0
    #pragma unroll
    for (int u = 0; u < 4; u++) {
        int c = u * 256 + tid;
        int gm = c >> 9;
        int rc = c & 511;
        int r = rc >> 3, cc = rc & 7;
        const __half* src = g_Qh + hoff + (size_t)((bx*2 + gm) * 64 + r) * 64 + cc * 8;
        cp16(sbase + oQ + (uint32_t)(gm * TQB + r * 144 + cc * 16), src);
    }
    #pragma unroll
    for (int u = 0; u < 4; u++) {
        int c = u * 256 + tid;
        int mat = c >> 9;
        int rc = c & 511;
        int r = rc >> 3, cc = rc & 7;
        const __half* src = (mat == 0 ? g_Kh : g_Vh) + hoff + (size_t)r * 64 + cc * 8;
        cp16(sbase + oKV + (uint32_t)(mat * TQB + r * 144 + cc * 16), src);
    }
    asm volatile("cp.async.commit_group;" ::: "memory");
    // preload group B: KV stage 1
    if (jtLast >= 1) {
        #pragma unroll
        for (int u = 0; u < 4; u++) {
            int c = u * 256 + tid;
            int mat = c >> 9;
            int rc = c & 511;
            int r = rc >> 3, cc = rc & 7;
            const __half* src = (mat == 0 ? g_Kh : g_Vh) + hoff + (size_t)(64 + r) * 64 + cc * 8;
            cp16(sbase + oKV + (uint32_t)(KVSTG + mat * TQB + r * 144 + cc * 16), src);
        }
        asm volatile("cp.async.commit_group;" ::: "memory");
    }

    const int qrow = lane >> 2;
    const int qcol = lane & 3;
    const int r0g = q0 + wr * 16 + qrow;
    const int r1g = r0g + 8;

    const int l7   = lane & 7;
    const int lb3  = (lane >> 3) & 1;
    const int lb4  = (lane >> 4) & 1;

    float o[8][4];
    #pragma unroll
    for (int nb = 0; nb < 8; nb++)
        #pragma unroll
        for (int k = 0; k < 4; k++) o[nb][k] = 0.f;
    float mr0 = -INFINITY, mr1 = -INFINITY, lr0 = 0.f, lr1 = 0.f;

    uint32_t qf[4][4];

    for (int jt = 0; jt <= jtLast; jt++) {
        const int t0 = jt * 64;
        if (jt < jtLast) { asm volatile("cp.async.wait_group 1;" ::: "memory"); }
        else             { asm volatile("cp.async.wait_group 0;" ::: "memory"); }
        __syncthreads();

        if (jt + 2 <= jtLast) {
            const int tn = (jt + 2) * 64;
            const uint32_t kvb = sbase + oKV + (uint32_t)(((jt + 2) % 3) * KVSTG);
            #pragma unroll
            for (int u = 0; u < 4; u++) {
                int c = u * 256 + tid;
                int mat = c >> 9;
                int rc = c & 511;
                int r = rc >> 3, cc = rc & 7;
                const __half* src = (mat == 0 ? g_Kh : g_Vh) + hoff + (size_t)(tn + r) * 64 + cc * 8;
                cp16(kvb + (uint32_t)(mat * TQB + r * 144 + cc * 16), src);
            }
            asm volatile("cp.async.commit_group;" ::: "memory");
        }

        if (jt == 0) {
            #pragma unroll
            for (int ks = 0; ks < 4; ks++) {
                uint32_t a = sQbase + (uint32_t)((wr*16 + l7 + lb3*8) * 144 + (ks*16 + lb4*8) * 2);
                ldsm4(qf[ks], a);
            }
        }

        const bool act = (padb == 0) || (jt <= qt && t0 < tlim);
        if (act) {
            const uint32_t kb = sbase + oKV + (uint32_t)((jt % 3) * KVSTG);
            const uint32_t vb = kb + TQB;

            float sc[8][4];
            #pragma unroll
            for (int nb = 0; nb < 8; nb++)
                #pragma unroll
                for (int k = 0; k < 4; k++) sc[nb][k] = 0.f;

            #pragma unroll
            for (int ds = 0; ds < 4; ds++) {
                #pragma unroll
                for (int tp = 0; tp < 4; tp++) {
                    uint32_t a = kb + (uint32_t)((tp*16 + l7 + lb4*8) * 144 + (ds*16 + lb3*8) * 2);
                    uint32_t kf[4];
                    ldsm4(kf, a);
                    mma16816(sc[2*tp],   qf[ds][0], qf[ds][1], qf[ds][2], qf[ds][3], kf[0], kf[1]);
                    mma16816(sc[2*tp+1], qf[ds][0], qf[ds][1], qf[ds][2], qf[ds][3], kf[2], kf[3]);
                }
            }

            float m0 = -INFINITY, m1 = -INFINITY;
            #pragma unroll
            for (int nb = 0; nb < 8; nb++) {
                const int tb = t0 + nb*8 + qcol*2;
                float v0 = sc[nb][0];
                float v1 = sc[nb][1];
                float v2 = sc[nb][2];
                float v3 = sc[nb][3];
                if ((tb   > r0g) | (tb   >= tlim) | (padb == 0)) v0 -= 1e9f;
                if ((tb+1 > r0g) | (tb+1 >= tlim) | (padb == 0)) v1 -= 1e9f;
                if ((tb   > r1g) | (tb   >= tlim) | (padb == 0)) v2 -= 1e9f;
                if ((tb+1 > r1g) | (tb+1 >= tlim) | (padb == 0)) v3 -= 1e9f;
                sc[nb][0] = v0; sc[nb][1] = v1; sc[nb][2] = v2; sc[nb][3] = v3;
                m0 = fmaxf(m0, fmaxf(v0, v1));
                m1 = fmaxf(m1, fmaxf(v2, v3));
            }
            m0 = fmaxf(m0, __shfl_xor_sync(0xffffffffu, m0, 1));
            m0 = fmaxf(m0, __shfl_xor_sync(0xffffffffu, m0, 2));
            m1 = fmaxf(m1, __shfl_xor_sync(0xffffffffu, m1, 1));
            m1 = fmaxf(m1, __shfl_xor_sync(0xffffffffu, m1, 2));
            const float mn0 = fmaxf(mr0, m0);
            const float mn1 = fmaxf(mr1, m1);
            const float a0 = __expf(mr0 - mn0);
            const float a1 = __expf(mr1 - mn1);

            uint32_t pl[8], ph[8];
            float ls0 = 0.f, ls1 = 0.f;
            #pragma unroll
            for (int nb = 0; nb < 8; nb++) {
                float p0 = __expf(sc[nb][0] - mn0);
                float p1 = __expf(sc[nb][1] - mn0);
                float p2 = __expf(sc[nb][2] - mn1);
                float p3 = __expf(sc[nb][3] - mn1);
                ls0 += p0 + p1;
                ls1 += p2 + p3;
                pl[nb] = pack2h(p0, p1);
                ph[nb] = pack2h(p2, p3);
                o[nb][0] *= a0; o[nb][1] *= a0;
                o[nb][2] *= a1; o[nb][3] *= a1;
            }
            ls0 += __shfl_xor_sync(0xffffffffu, ls0, 1);
            ls0 += __shfl_xor_sync(0xffffffffu, ls0, 2);
            ls1 += __shfl_xor_sync(0xffffffffu, ls1, 1);
            ls1 += __shfl_xor_sync(0xffffffffu, ls1, 2);
            lr0 = lr0 * a0 + ls0;
            lr1 = lr1 * a1 + ls1;
            mr0 = mn0; mr1 = mn1;

            #pragma unroll
            for (int ks = 0; ks < 4; ks++) {
                const uint32_t pa0 = pl[2*ks],   pa1 = ph[2*ks];
                const uint32_t pa2 = pl[2*ks+1], pa3 = ph[2*ks+1];
                #pragma unroll
                for (int dp = 0; dp < 4; dp++) {
                    uint32_t a = vb + (uint32_t)((ks*16 + l7 + lb3*8) * 144 + (dp*16 + lb4*8) * 2);
                    uint32_t vf[4];
                    ldsm4t(vf, a);
                    mma16816(o[2*dp],   pa0, pa1, pa2, pa3, vf[0], vf[1]);
                    mma16816(o[2*dp+1], pa0, pa1, pa2, pa3, vf[2], vf[3]);
                }
            }
        }
    }

    // epilogue: fp32 bounce buffer overlays the (dead) KV region
    __syncthreads();
    float* sSg = (float*)(sm + oKV + g * 17408);
    {
        const float inv0 = 1.f / lr0;
        const float inv1 = 1.f / lr1;
        float* d0 = sSg + (wr*16 + qrow) * SLD + qcol*2;
        float* d1 = d0 + 8 * SLD;
        #pragma unroll
        for (int nb = 0; nb < 8; nb++) {
            d0[nb*8]     = o[nb][0] * inv0;
            d0[nb*8 + 1] = o[nb][1] * inv0;
            d1[nb*8]     = o[nb][2] * inv1;
            d1[nb*8 + 1] = o[nb][3] * inv1;
        }
    }
    __syncwarp();
    {
        const int lr_ = lane >> 1, half = lane & 1;
        const int srow = q0 + wr * 16 + lr_;
        const float* Or = sSg + (wr*16 + lr_) * SLD + half * 32;
        const size_t base = ((size_t)(b * S_ + srow)) * DM_ + h * 64 + half * 32;
        #pragma unroll
        for (int c = 0; c < 32; c += 2)
            *(uint32_t*)(g_Ac0 + base + c) = pack2h(Or[c], Or[c+1]);
    }
}

// ---------------------------------------------------------------------------
extern "C" void kernel_launch(void* const* d_in, const int* in_sizes, int n_in,
                              void* d_out, int out_size)
{
    const float* Q   = (const float*)d_in[0];
    const float* K   = (const float*)d_in[1];
    const float* V   = (const float*)d_in[2];
    const int*   pad = (const int*)  d_in[3];
    const float* Wq  = (const float*)d_in[4];
    const float* bq  = (const float*)d_in[5];
    const float* Wk  = (const float*)d_in[6];
    const float* bk  = (const float*)d_in[7];
    const float* Wv  = (const float*)d_in[8];
    const float* bv  = (const float*)d_in[9];
    const float* Wo  = (const float*)d_in[10];
    const float* bo  = (const float*)d_in[11];
    float* out = (float*)d_out;

    cudaFuncSetAttribute(mma_gemm_h1b,
                         cudaFuncAttributeMaxDynamicSharedMemorySize, GSMEM1);
    cudaFuncSetAttribute(mma_gemm_h1f,
                         cudaFuncAttributeMaxDynamicSharedMemorySize, GSMEMO);
    cudaFuncSetAttribute(attn_mma,
                         cudaFuncAttributeMaxDynamicSharedMemorySize, ATTN_SMEM);

    const int n4 = (B_*S_*DM_) / 4;

    cvt_act_h3<<<dim3(n4/256, 3), 256>>>((const float4*)Q, (const float4*)K,
                                         (const float4*)V, n4);
    split_wT_h4<<<dim3(32, 32, 4), dim3(32, 8)>>>(Wq, Wk, Wv, Wo);
    mma_gemm_h1b<<<dim3(8, 64, 3), 128, GSMEM1>>>(bq, bk, bv);

    attn_mma<<<dim3(8, 128), 256, ATTN_SMEM>>>(pad);

    mma_gemm_h1f<<<dim3(8, 64), 128, GSMEMO>>>(bo, out);
}

// round 17
// speedup vs baseline: 1.0280x; 1.0280x over previous
#include <cuda_runtime.h>
#include <cuda_bf16.h>
#include <cuda_fp16.h>
#include <mma.h>
#include <math.h>
#include <stdint.h>

using namespace nvcuda;

#define S_   1024
#define DM_  1024
#define B_   8
#define H_   16
#define D_   64

// ---------------- scratch (__device__ globals; no allocation) ----------------
__device__ __half g_Qh[B_*H_*S_*D_];   // projected Q (pre-scaled by 1/32) fp16
__device__ __half g_Kh[B_*H_*S_*D_];   // projected K
__device__ __half g_Vh[B_*H_*S_*D_];   // projected V
__device__ __half g_Ac0[B_*S_*DM_];    // converted Q input; then X fp16
__device__ __half g_Ac1[B_*S_*DM_];    // converted K input
__device__ __half g_Ac2[B_*S_*DM_];    // converted V input
__device__ __half g_W4[4*DM_*DM_];     // transposed fp16 weights [n][k]: Wq,Wk,Wv,Wo

// ---------------- helpers ----------------
__device__ __forceinline__ uint32_t smem_u32(const void* p) {
    uint32_t a;
    asm("{ .reg .u64 t; cvta.to.shared.u64 t, %1; cvt.u32.u64 %0, t; }"
        : "=r"(a) : "l"(p));
    return a;
}
__device__ __forceinline__ void cp16(uint32_t dst, const void* src) {
    asm volatile("cp.async.cg.shared.global [%0], [%1], 16;" :: "r"(dst), "l"(src));
}
__device__ __forceinline__ uint32_t pack2h(float a, float b) {
    __half ha = __float2half_rn(a), hb = __float2half_rn(b);
    return (uint32_t)__half_as_ushort(ha) |
           ((uint32_t)__half_as_ushort(hb) << 16);
}
__device__ __forceinline__ void ldsm4(uint32_t* r, uint32_t addr) {
    asm volatile("ldmatrix.sync.aligned.m8n8.x4.shared.b16 {%0,%1,%2,%3}, [%4];"
        : "=r"(r[0]), "=r"(r[1]), "=r"(r[2]), "=r"(r[3]) : "r"(addr));
}
__device__ __forceinline__ void ldsm4t(uint32_t* r, uint32_t addr) {
    asm volatile("ldmatrix.sync.aligned.m8n8.x4.trans.shared.b16 {%0,%1,%2,%3}, [%4];"
        : "=r"(r[0]), "=r"(r[1]), "=r"(r[2]), "=r"(r[3]) : "r"(addr));
}
__device__ __forceinline__ void mma16816(float* c,
    uint32_t a0, uint32_t a1, uint32_t a2, uint32_t a3, uint32_t b0, uint32_t b1) {
    asm volatile(
        "mma.sync.aligned.m16n8k16.row.col.f32.f16.f16.f32 "
        "{%0,%1,%2,%3}, {%4,%5,%6,%7}, {%8,%9}, {%0,%1,%2,%3};"
        : "+f"(c[0]), "+f"(c[1]), "+f"(c[2]), "+f"(c[3])
        : "r"(a0), "r"(a1), "r"(a2), "r"(a3), "r"(b0), "r"(b1));
}

// ---------------- conversion kernels (batched over z) ----------------
__global__ __launch_bounds__(256) void cvt_act_h3(
    const float4* __restrict__ Q, const float4* __restrict__ K,
    const float4* __restrict__ V, int n4)
{
    int i = blockIdx.x * 256 + threadIdx.x;
    if (i >= n4) return;
    int z = blockIdx.y;
    const float4* src = (z == 0) ? Q : (z == 1) ? K : V;
    uint2* dst = (uint2*)((z == 0) ? g_Ac0 : (z == 1) ? g_Ac1 : g_Ac2);
    float4 v = src[i];
    uint2 h;
    h.x = pack2h(v.x, v.y);
    h.y = pack2h(v.z, v.w);
    dst[i] = h;
}

// weight transpose fp16, 4-way batch: z<3 src=W[h][k][d] (n=h*64+d); z=3 src=Wo[k][n]
__global__ __launch_bounds__(256) void split_wT_h4(
    const float* __restrict__ Wq, const float* __restrict__ Wk,
    const float* __restrict__ Wv, const float* __restrict__ Wo)
{
    __shared__ float t[32][33];
    int k0 = blockIdx.x * 32, n0 = blockIdx.y * 32;
    int z = blockIdx.z;
    const float* W = (z == 0) ? Wq : (z == 1) ? Wk : (z == 2) ? Wv : Wo;
    __half* out = g_W4 + (size_t)z * DM_ * DM_;
    int tx = threadIdx.x, ty = threadIdx.y;
    #pragma unroll
    for (int i = 0; i < 4; i++) {
        int k = k0 + ty + 8*i, n = n0 + tx;
        float v = (z < 3) ? W[(((size_t)(n >> 6)) * 1024 + k) * 64 + (n & 63)]
                          : W[(size_t)k * 1024 + n];
        t[ty + 8*i][tx] = v;
    }
    __syncthreads();
    #pragma unroll
    for (int i = 0; i < 4; i++) {
        int n = n0 + ty + 8*i, k = k0 + tx;
        out[(size_t)n * 1024 + k] = __float2half_rn(t[tx][ty + 8*i]);
    }
}

// ---------------- fragment typedefs / sizes ----------------
#define LDSM   40
#define MATB   (128 * LDSM * 2)
#define STAGEB1 (2 * MATB)
#define EPLD   132
#define GSMEM1 (128 * EPLD * 4)                  // proj: epilogue roundtrip 67584
#define GSMEMO (2 * STAGEB1 + 16 * 128 * 4)      // out: mainloop only 49152

typedef wmma::fragment<wmma::matrix_a, 16,16,16, __half, wmma::row_major> HFragA;
typedef wmma::fragment<wmma::matrix_b, 16,16,16, __half, wmma::col_major> HFragB;
typedef wmma::fragment<wmma::accumulator, 16,16,16, float> FragC;

// ---------------- fp16 single-pass GEMM stage loader ------------------------
__device__ __forceinline__ void issue_stage_h1(
    const __half* __restrict__ Ah, const __half* __restrict__ Bh,
    uint32_t sbase, int stage, int m0, int n0, int k0, int tid)
{
    #pragma unroll
    for (int u = 0; u < 8; u++) {
        int chunk = u * 128 + tid;
        int mat = chunk >> 9;
        int r   = (chunk >> 2) & 127;
        int c   = chunk & 3;
        const __half* g = (mat == 0)
            ? Ah + (size_t)(m0 + r) * 1024 + k0 + c * 8
            : Bh + (size_t)(n0 + r) * 1024 + k0 + c * 8;
        uint32_t dst = sbase + (uint32_t)(stage * STAGEB1 + mat * MATB + r * (LDSM*2) + c * 16);
        cp16(dst, g);
    }
    asm volatile("cp.async.commit_group;" ::: "memory");
}

// ---------------- fp16 single-pass GEMM, batched QKV projections ------------
__global__ __launch_bounds__(128, 2) void mma_gemm_h1b(
    const float* __restrict__ bq, const float* __restrict__ bk,
    const float* __restrict__ bv)
{
    extern __shared__ char sm[];
    float* sBias = (float*)(sm + 2 * STAGEB1);
    const uint32_t sbase = smem_u32(sm);
    const int tid = threadIdx.x;
    const int wid = tid >> 5;
    const int m0 = blockIdx.y * 128;
    const int n0 = blockIdx.x * 128;
    const int z  = blockIdx.z;
    const int wm = wid >> 1;
    const int wn = wid & 1;

    const __half* Ah = (z == 0) ? g_Ac0 : (z == 1) ? g_Ac1 : g_Ac2;
    const __half* Bh = g_W4 + (size_t)z * DM_ * DM_;
    const float* bias = (z == 0) ? bq : (z == 1) ? bk : bv;
    __half* outH = (z == 0) ? g_Qh : (z == 1) ? g_Kh : g_Vh;
    const float osc = (z == 0) ? 0.03125f : 1.0f;   // fold 1/32 into Q (exact)

    for (int idx = tid; idx < 16 * 128; idx += 128)
        sBias[idx] = bias[n0 + (idx & 127)];
    __syncthreads();

    FragC acc[4][4];
    #pragma unroll
    for (int i = 0; i < 4; i++)
        #pragma unroll
        for (int j = 0; j < 4; j++)
            wmma::load_matrix_sync(acc[i][j], sBias + wn*64 + j*16, 128, wmma::mem_row_major);

    issue_stage_h1(Ah, Bh, sbase, 0, m0, n0, 0, tid);

    for (int kc = 0; kc < 32; kc++) {
        const int s = kc & 1;
        if (kc + 1 < 32) {
            issue_stage_h1(Ah, Bh, sbase, s ^ 1, m0, n0, (kc + 1) * 32, tid);
            asm volatile("cp.async.wait_group 1;" ::: "memory");
        } else {
            asm volatile("cp.async.wait_group 0;" ::: "memory");
        }
        __syncthreads();

        const __half* stg = (const __half*)(sm + s * STAGEB1);
        const __half* sAh = stg;
        const __half* sBh = stg + 128 * LDSM;

        #pragma unroll
        for (int ks = 0; ks < 2; ks++) {
            HFragA ah[4];
            HFragB bh[4];
            #pragma unroll
            for (int i = 0; i < 4; i++)
                wmma::load_matrix_sync(ah[i], sAh + (wm*64 + i*16) * LDSM + ks*16, LDSM);
            #pragma unroll
            for (int j = 0; j < 4; j++)
                wmma::load_matrix_sync(bh[j], sBh + (wn*64 + j*16) * LDSM + ks*16, LDSM);
            #pragma unroll
            for (int i = 0; i < 4; i++)
                #pragma unroll
                for (int j = 0; j < 4; j++)
                    wmma::mma_sync(acc[i][j], ah[i], bh[j], acc[i][j]);
        }
        __syncthreads();
    }

    float* sEpi = (float*)sm;
    #pragma unroll
    for (int i = 0; i < 4; i++)
        #pragma unroll
        for (int j = 0; j < 4; j++)
            wmma::store_matrix_sync(sEpi + (wm*64 + i*16) * EPLD + wn*64 + j*16,
                                    acc[i][j], EPLD, wmma::mem_row_major);
    __syncthreads();

    #pragma unroll
    for (int u = 0; u < 64; u++) {
        int e2 = u * 128 + tid;
        int r = e2 >> 6;
        int c = (e2 & 63) * 2;
        float v0 = sEpi[r * EPLD + c]     * osc;
        float v1 = sEpi[r * EPLD + c + 1] * osc;
        uint32_t hv = pack2h(v0, v1);
        const int m = m0 + r, n = n0 + c;
        const int b = m >> 10, srow = m & 1023;
        const int h = n >> 6,  d = n & 63;
        size_t addr = ((((size_t)(b*16 + h)) * 1024 + srow) * 64 + d);
        *(uint32_t*)(outH + addr) = hv;
    }
}

// ---------------- fp16 single-pass GEMM (output projection, fp32 out) -------
__global__ __launch_bounds__(128, 2) void mma_gemm_h1f(
    const float* __restrict__ bias, float* __restrict__ outF)
{
    extern __shared__ char sm[];
    float* sBias = (float*)(sm + 2 * STAGEB1);
    const uint32_t sbase = smem_u32(sm);
    const int tid = threadIdx.x;
    const int wid = tid >> 5;
    const int m0 = blockIdx.y * 128;
    const int n0 = blockIdx.x * 128;
    const int wm = wid >> 1;
    const int wn = wid & 1;

    const __half* Ah = g_Ac0;                     // X fp16
    const __half* Bh = g_W4 + (size_t)3 * DM_ * DM_;  // Wo fp16 [n][k]

    for (int idx = tid; idx < 16 * 128; idx += 128)
        sBias[idx] = bias[n0 + (idx & 127)];
    __syncthreads();

    FragC acc[4][4];
    #pragma unroll
    for (int i = 0; i < 4; i++)
        #pragma unroll
        for (int j = 0; j < 4; j++)
            wmma::load_matrix_sync(acc[i][j], sBias + wn*64 + j*16, 128, wmma::mem_row_major);

    issue_stage_h1(Ah, Bh, sbase, 0, m0, n0, 0, tid);

    for (int kc = 0; kc < 32; kc++) {
        const int s = kc & 1;
        if (kc + 1 < 32) {
            issue_stage_h1(Ah, Bh, sbase, s ^ 1, m0, n0, (kc + 1) * 32, tid);
            asm volatile("cp.async.wait_group 1;" ::: "memory");
        } else {
            asm volatile("cp.async.wait_group 0;" ::: "memory");
        }
        __syncthreads();

        const __half* stg = (const __half*)(sm + s * STAGEB1);
        const __half* sAh = stg;
        const __half* sBh = stg + 128 * LDSM;

        #pragma unroll
        for (int ks = 0; ks < 2; ks++) {
            HFragA ah[4];
            HFragB bh[4];
            #pragma unroll
            for (int i = 0; i < 4; i++)
                wmma::load_matrix_sync(ah[i], sAh + (wm*64 + i*16) * LDSM + ks*16, LDSM);
            #pragma unroll
            for (int j = 0; j < 4; j++)
                wmma::load_matrix_sync(bh[j], sBh + (wn*64 + j*16) * LDSM + ks*16, LDSM);
            #pragma unroll
            for (int i = 0; i < 4; i++)
                #pragma unroll
                for (int j = 0; j < 4; j++)
                    wmma::mma_sync(acc[i][j], ah[i], bh[j], acc[i][j]);
        }
        __syncthreads();
    }

    #pragma unroll
    for (int i = 0; i < 4; i++) {
        const int m = m0 + wm*64 + i*16;
        #pragma unroll
        for (int j = 0; j < 4; j++) {
            const int n = n0 + wn*64 + j*16;
            wmma::store_matrix_sync(outF + (size_t)m * 1024 + n, acc[i][j],
                                    1024, wmma::mem_row_major);
        }
    }
}

// ---------------- flash attention v6 (R15 layout; Q pre-scaled) -------------
#define ALD 72
#define SLD 68
#define TQB 9216
#define oQ   0
#define oKV  18432
#define oS   55296
#define ATTN_SMEM 90112
#define KVSTG (2 * TQB)

__global__ __launch_bounds__(256, 2) void attn_mma(const int* __restrict__ pad)
{
    extern __shared__ char sm[];
    const uint32_t sbase = smem_u32(sm);
    const int tid  = threadIdx.x;
    const int w    = tid >> 5, lane = tid & 31;
    const int g    = w >> 2,   wr   = w & 3;
    const int bx   = blockIdx.x;
    const int bh   = blockIdx.y;
    const int b    = bh >> 4, h = bh & 15;
    const int padb = pad[b];
    const int tlim = S_ - padb;
    const int qt   = bx * 2 + g;
    const int q0   = qt * 64;
    const size_t hoff = (size_t)bh * S_ * D_;

    float* sSg = (float*)(sm + oS + g * 17408);
    const uint32_t sQbase = sbase + oQ + (uint32_t)g * TQB;

    #pragma unroll
    for (int u = 0; u < 4; u++) {
        int c = u * 256 + tid;
        int gm = c >> 9;
        int rc = c & 511;
        int r = rc >> 3, cc = rc & 7;
        const __half* src = g_Qh + hoff + (size_t)((bx*2 + gm) * 64 + r) * 64 + cc * 8;
        cp16(sbase + oQ + (uint32_t)(gm * TQB + r * 144 + cc * 16), src);
    }
    #pragma unroll
    for (int u = 0; u < 4; u++) {
        int c = u * 256 + tid;
        int mat = c >> 9;
        int rc = c & 511;
        int r = rc >> 3, cc = rc & 7;
        const __half* src = (mat == 0 ? g_Kh : g_Vh) + hoff + (size_t)r * 64 + cc * 8;
        cp16(sbase + oKV + (uint32_t)(mat * TQB + r * 144 + cc * 16), src);
    }
    asm volatile("cp.async.commit_group;" ::: "memory");

    const int jtLast = (padb == 0) ? 15 : min(bx * 2 + 1, (tlim - 1) >> 6);

    const int qrow = lane >> 2;
    const int qcol = lane & 3;
    const int r0g = q0 + wr * 16 + qrow;
    const int r1g = r0g + 8;

    const int l7   = lane & 7;
    const int lb3  = (lane >> 3) & 1;
    const int lb4  = (lane >> 4) & 1;

    float o[8][4];
    #pragma unroll
    for (int nb = 0; nb < 8; nb++)
        #pragma unroll
        for (int k = 0; k < 4; k++) o[nb][k] = 0.f;
    float mr0 = -INFINITY, mr1 = -INFINITY, lr0 = 0.f, lr1 = 0.f;

    uint32_t qf[4][4];

    for (int jt = 0; jt <= jtLast; jt++) {
        const int s = jt & 1;
        const int t0 = jt * 64;
        if (jt < jtLast) {
            const int tn = (jt + 1) * 64;
            #pragma unroll
            for (int u = 0; u < 4; u++) {
                int c = u * 256 + tid;
                int mat = c >> 9;
                int rc = c & 511;
                int r = rc >> 3, cc = rc & 7;
                const __half* src = (mat == 0 ? g_Kh : g_Vh) + hoff + (size_t)(tn + r) * 64 + cc * 8;
                cp16(sbase + oKV + (uint32_t)((s ^ 1) * KVSTG + mat * TQB + r * 144 + cc * 16), src);
            }
            asm volatile("cp.async.commit_group;" ::: "memory");
            asm volatile("cp.async.wait_group 1;" ::: "memory");
        } else {
            asm volatile("cp.async.wait_group 0;" ::: "memory");
        }
        __syncthreads();

        if (jt == 0) {
            #pragma unroll
            for (int ks = 0; ks < 4; ks++) {
                uint32_t a = sQbase + (uint32_t)((wr*16 + l7 + lb3*8) * 144 + (ks*16 + lb4*8) * 2);
                ldsm4(qf[ks], a);
            }
        }

        const bool act = (padb == 0) || (jt <= qt && t0 < tlim);
        if (act) {
            const uint32_t kb = sbase + oKV + (uint32_t)(s * KVSTG);
            const uint32_t vb = kb + TQB;

            float sc[8][4];
            #pragma unroll
            for (int nb = 0; nb < 8; nb++)
                #pragma unroll
                for (int k = 0; k < 4; k++) sc[nb][k] = 0.f;

            #pragma unroll
            for (int ds = 0; ds < 4; ds++) {
                #pragma unroll
                for (int tp = 0; tp < 4; tp++) {
                    uint32_t a = kb + (uint32_t)((tp*16 + l7 + lb4*8) * 144 + (ds*16 + lb3*8) * 2);
                    uint32_t kf[4];
                    ldsm4(kf, a);
                    mma16816(sc[2*tp],   qf[ds][0], qf[ds][1], qf[ds][2], qf[ds][3], kf[0], kf[1]);
                    mma16816(sc[2*tp+1], qf[ds][0], qf[ds][1], qf[ds][2], qf[ds][3], kf[2], kf[3]);
                }
            }

            // Q pre-scaled by 1/32 -> scores already scaled (bit-identical)
            float m0 = -INFINITY, m1 = -INFINITY;
            #pragma unroll
            for (int nb = 0; nb < 8; nb++) {
                const int tb = t0 + nb*8 + qcol*2;
                float v0 = sc[nb][0];
                float v1 = sc[nb][1];
                float v2 = sc[nb][2];
                float v3 = sc[nb][3];
                if ((tb   > r0g) | (tb   >= tlim) | (padb == 0)) v0 -= 1e9f;
                if ((tb+1 > r0g) | (tb+1 >= tlim) | (padb == 0)) v1 -= 1e9f;
                if ((tb   > r1g) | (tb   >= tlim) | (padb == 0)) v2 -= 1e9f;
                if ((tb+1 > r1g) | (tb+1 >= tlim) | (padb == 0)) v3 -= 1e9f;
                sc[nb][0] = v0; sc[nb][1] = v1; sc[nb][2] = v2; sc[nb][3] = v3;
                m0 = fmaxf(m0, fmaxf(v0, v1));
                m1 = fmaxf(m1, fmaxf(v2, v3));
            }
            m0 = fmaxf(m0, __shfl_xor_sync(0xffffffffu, m0, 1));
            m0 = fmaxf(m0, __shfl_xor_sync(0xffffffffu, m0, 2));
            m1 = fmaxf(m1, __shfl_xor_sync(0xffffffffu, m1, 1));
            m1 = fmaxf(m1, __shfl_xor_sync(0xffffffffu, m1, 2));
            const float mn0 = fmaxf(mr0, m0);
            const float mn1 = fmaxf(mr1, m1);
            const float a0 = __expf(mr0 - mn0);
            const float a1 = __expf(mr1 - mn1);

            uint32_t pl[8], ph[8];
            float ls0 = 0.f, ls1 = 0.f;
            #pragma unroll
            for (int nb = 0; nb < 8; nb++) {
                float p0 = __expf(sc[nb][0] - mn0);
                float p1 = __expf(sc[nb][1] - mn0);
                float p2 = __expf(sc[nb][2] - mn1);
                float p3 = __expf(sc[nb][3] - mn1);
                ls0 += p0 + p1;
                ls1 += p2 + p3;
                pl[nb] = pack2h(p0, p1);
                ph[nb] = pack2h(p2, p3);
                o[nb][0] *= a0; o[nb][1] *= a0;
                o[nb][2] *= a1; o[nb][3] *= a1;
            }
            ls0 += __shfl_xor_sync(0xffffffffu, ls0, 1);
            ls0 += __shfl_xor_sync(0xffffffffu, ls0, 2);
            ls1 += __shfl_xor_sync(0xffffffffu, ls1, 1);
            ls1 += __shfl_xor_sync(0xffffffffu, ls1, 2);
            lr0 = lr0 * a0 + ls0;
            lr1 = lr1 * a1 + ls1;
            mr0 = mn0; mr1 = mn1;

            #pragma unroll
            for (int ks = 0; ks < 4; ks++) {
                const uint32_t pa0 = pl[2*ks],   pa1 = ph[2*ks];
                const uint32_t pa2 = pl[2*ks+1], pa3 = ph[2*ks+1];
                #pragma unroll
                for (int dp = 0; dp < 4; dp++) {
                    uint32_t a = vb + (uint32_t)((ks*16 + l7 + lb3*8) * 144 + (dp*16 + lb4*8) * 2);
                    uint32_t vf[4];
                    ldsm4t(vf, a);
                    mma16816(o[2*dp],   pa0, pa1, pa2, pa3, vf[0], vf[1]);
                    mma16816(o[2*dp+1], pa0, pa1, pa2, pa3, vf[2], vf[3]);
                }
            }
        }
        __syncthreads();
    }

    // epilogue: normalize in registers, bounce via smem, write X fp16
    {
        const float inv0 = 1.f / lr0;
        const float inv1 = 1.f / lr1;
        float* d0 = sSg + (wr*16 + qrow) * SLD + qcol*2;
        float* d1 = d0 + 8 * SLD;
        #pragma unroll
        for (int nb = 0; nb < 8; nb++) {
            d0[nb*8]     = o[nb][0] * inv0;
            d0[nb*8 + 1] = o[nb][1] * inv0;
            d1[nb*8]     = o[nb][2] * inv1;
            d1[nb*8 + 1] = o[nb][3] * inv1;
        }
    }
    __syncwarp();
    {
        const int lr_ = lane >> 1, half = lane & 1;
        const int srow = q0 + wr * 16 + lr_;
        const float* Or = sSg + (wr*16 + lr_) * SLD + half * 32;
        const size_t base = ((size_t)(b * S_ + srow)) * DM_ + h * 64 + half * 32;
        #pragma unroll
        for (int c = 0; c < 32; c += 2)
            *(uint32_t*)(g_Ac0 + base + c) = pack2h(Or[c], Or[c+1]);
    }
}

// ---------------------------------------------------------------------------
extern "C" void kernel_launch(void* const* d_in, const int* in_sizes, int n_in,
                              void* d_out, int out_size)
{
    const float* Q   = (const float*)d_in[0];
    const float* K   = (const float*)d_in[1];
    const float* V   = (const float*)d_in[2];
    const int*   pad = (const int*)  d_in[3];
    const float* Wq  = (const float*)d_in[4];
    const float* bq  = (const float*)d_in[5];
    const float* Wk  = (const float*)d_in[6];
    const float* bk  = (const float*)d_in[7];
    const float* Wv  = (const float*)d_in[8];
    const float* bv  = (const float*)d_in[9];
    const float* Wo  = (const float*)d_in[10];
    const float* bo  = (const float*)d_in[11];
    float* out = (float*)d_out;

    cudaFuncSetAttribute(mma_gemm_h1b,
                         cudaFuncAttributeMaxDynamicSharedMemorySize, GSMEM1);
    cudaFuncSetAttribute(mma_gemm_h1f,
                         cudaFuncAttributeMaxDynamicSharedMemorySize, GSMEMO);
    cudaFuncSetAttribute(attn_mma,
                         cudaFuncAttributeMaxDynamicSharedMemorySize, ATTN_SMEM);

    const int n4 = (B_*S_*DM_) / 4;

    cvt_act_h3<<<dim3(n4/256, 3), 256>>>((const float4*)Q, (const float4*)K,
                                         (const float4*)V, n4);
    split_wT_h4<<<dim3(32, 32, 4), dim3(32, 8)>>>(Wq, Wk, Wv, Wo);
    mma_gemm_h1b<<<dim3(8, 64, 3), 128, GSMEM1>>>(bq, bk, bv);

    attn_mma<<<dim3(8, 128), 256, ATTN_SMEM>>>(pad);

    mma_gemm_h1f<<<dim3(8, 64), 128, GSMEMO>>>(bo, out);
}